// round 10
// baseline (speedup 1.0000x reference)
#include <cuda_runtime.h>
#include <cstdint>

// OccupancyPooling: N=8192, 6x6 relative occupancy over all 67M pairs, then
// Linear(36 -> 128).
//
// R10 = R5 structure (best: 45.5us) with two count-phase reductions:
//  - CHUNK=512 / S=16: per-block zero/flush overhead amortized 4x
//    (0.84 -> 0.21 inst/pair); partials shrink 18.9MB -> 4.7MB (4x less u8
//    store traffic + 4x cheaper epilogue reduce)
//  - j-data read via broadcast __ldg float4 (obs = 64KB, L1-resident; 1
//    sector/request) instead of smem staging: frees 0.5 crossbar
//    wavefronts/pair (crossbar is the co-binding resource at 1 wf/cyc/SM)
//    and deletes the staging loop + syncthreads
//  - count math unchanged: bit-exact 3-op packed form (R8 proved 2-op worse)
//  - epilogue: R5 fused dp4a reduce + ROWS2=32 broadcast GEMM, 16 partials,
//    self-pair subtract at cell 21 (guaranteed by bit-exact math)

#define N_AGENTS 8192
#define NCELL    36
#define HIDDEN   128
#define T1       128
#define CHUNK    512                    // 16 chunks * 512 = 8192 exact
#define S_CHUNKS 16
#define I_TILES  (N_AGENTS / T1)        // 64 -> grid 64x16 = 1024 blocks

#define T2       256
#define ROWS2    32                     // 256 gemm blocks

// Partial histograms [chunk][cell][agent] u8. Max realistic count/chunk ~45
// (512 gaussian j's, peak cell prob ~4%) << 255. Fully rewritten every
// launch -> deterministic, no zeroing.
__device__ unsigned char g_part[S_CHUNKS][NCELL][N_AGENTS];

__device__ __forceinline__ unsigned long long pack2(float lo, float hi) {
    unsigned long long r;
    asm("mov.b64 %0, {%1, %2};" : "=l"(r) : "f"(lo), "f"(hi));
    return r;
}

// One pair, bit-exact vs reference:
//   d = rn(pj - pi)       packed FADD2 (negation exact)
//   r = rn(d*2 + 3)       packed FFMA2 (d*2 exact -> single rounding == ref)
//   m = rd(r + 2^23)      packed FADD2.RM magic floor: bits = 0x4B000000 +
//                         floor(r) for r in [0,2^23); bits < 0x4B000000 if r<0
__device__ __forceinline__ void count_pair(unsigned long long xy,
                                           unsigned long long negxy,
                                           unsigned long long two2,
                                           unsigned long long three2,
                                           unsigned long long magic2,
                                           char* __restrict__ cnt_t) {
    unsigned long long d, r, m;
    asm("add.rn.f32x2 %0, %1, %2;" : "=l"(d) : "l"(xy), "l"(negxy));
    asm("fma.rn.f32x2 %0, %1, %2, %3;" : "=l"(r) : "l"(d), "l"(two2), "l"(three2));
    asm("add.rm.f32x2 %0, %1, %2;" : "=l"(m) : "l"(r), "l"(magic2));
    unsigned bu, bv;
    asm("mov.b64 {%0, %1}, %2;" : "=r"(bu), "=r"(bv) : "l"(m));
    // byte offset: (bu*6+bv)*512 wraps (mod 2^32) to slot*512 exactly
    // (7*0x4B000000*512 == 26*2^32) -- no bias subtraction needed.
    const unsigned offb = (bu * 6u + bv) * 512u;
    if ((bu - 0x4B000000u) < 6u && (bv - 0x4B000000u) < 6u)
        *(unsigned*)(cnt_t + offb) += 1u;   // [slot][tid]: bank=tid%32, no conflicts
}

__global__ __launch_bounds__(T1, 12) void occ_count_kernel(const float2* __restrict__ obs) {
    __shared__ unsigned cnt[NCELL * T1];           // [slot][tid], 18432 B

    const int tid = threadIdx.x;
    const int i   = blockIdx.x * T1 + tid;
    const int s   = blockIdx.y;

    #pragma unroll
    for (int c = 0; c < NCELL; c++) cnt[c * T1 + tid] = 0u;

    const float2 pi = obs[i];
    const unsigned long long negxy  = pack2(-pi.x, -pi.y);
    const unsigned long long two2   = pack2(2.0f, 2.0f);
    const unsigned long long three2 = pack2(3.0f, 3.0f);
    const unsigned long long magic2 = pack2(8388608.0f, 8388608.0f);
    char* cnt_t = (char*)(cnt + tid);

    __syncthreads();   // cnt zeroing visible block-wide (same-thread slots anyway)

    // j data via broadcast L1-resident LDG.128 (all lanes same address:
    // 1 sector/request) -- keeps the smem crossbar free for the RMW.
    const float4* j4 = (const float4*)(obs + s * CHUNK);   // 256 float4
    #pragma unroll 8
    for (int jj = 0; jj < CHUNK / 2; jj++) {
        const float4 p = __ldg(j4 + jj);
        unsigned long long xy0, xy1;
        asm("mov.b64 %0, {%1, %2};" : "=l"(xy0) : "f"(p.x), "f"(p.y));
        asm("mov.b64 %0, {%1, %2};" : "=l"(xy1) : "f"(p.z), "f"(p.w));
        count_pair(xy0, negxy, two2, three2, magic2, cnt_t);
        count_pair(xy1, negxy, two2, three2, magic2, cnt_t);
    }

    #pragma unroll
    for (int c = 0; c < NCELL; c++)
        g_part[s][c][i] = (unsigned char)cnt[c * T1 + tid];   // coalesced u8
}

// Fused reduce + GEMM (g_part 4.7MB -> L2-hot during graph replay).
// Phase A: 288 (cell, 4-row quad) items; each sums 16 u8 partials with
//          UNSIGNED dp4a byte extraction; subtract self pair (bit-exact math
//          puts j==i at rel=(3,3) -> cell 21, always).
// Phase B: out[r,:] = occs[r,:] @ W.T + b, stride-37 smem W (conflict-free).
__global__ __launch_bounds__(T2) void occ_gemm_kernel(
    const float* __restrict__ W,   // [128, 36] row-major
    const float* __restrict__ b,   // [128]
    float* __restrict__ out)       // [8192, 128]
{
    __shared__ float Ws[HIDDEN * 37];          // 18944 B
    __shared__ float occs[ROWS2 * NCELL];      // 4608 B

    const int tid   = threadIdx.x;
    const int rbase = blockIdx.x * ROWS2;

    for (int idx = tid; idx < HIDDEN * NCELL; idx += T2) {
        const int h = idx / NCELL, c = idx - h * NCELL;
        Ws[h * 37 + c] = W[idx];
    }

    for (int id = tid; id < NCELL * (ROWS2 / 4); id += T2) {   // 288 items
        const int c = id >> 3;
        const int q = id & 7;
        unsigned a0 = 0, a1 = 0, a2 = 0, a3 = 0;
        #pragma unroll
        for (int s = 0; s < S_CHUNKS; s++) {
            const unsigned w = *(const unsigned*)&g_part[s][c][rbase + q * 4];
            a0 = __dp4a(w, 0x00000001u, a0);
            a1 = __dp4a(w, 0x00000100u, a1);
            a2 = __dp4a(w, 0x00010000u, a2);
            a3 = __dp4a(w, 0x01000000u, a3);
        }
        const float self = (c == 21) ? 1.0f : 0.0f;
        occs[(q * 4 + 0) * NCELL + c] = (float)a0 - self;
        occs[(q * 4 + 1) * NCELL + c] = (float)a1 - self;
        occs[(q * 4 + 2) * NCELL + c] = (float)a2 - self;
        occs[(q * 4 + 3) * NCELL + c] = (float)a3 - self;
    }
    __syncthreads();

    const int h  = tid & (HIDDEN - 1);         // lanes -> consecutive h
    const int hy = tid >> 7;                   // row half (uniform per warp)
    const float bh = b[h];

    float acc[16];
    #pragma unroll
    for (int k = 0; k < 16; k++) acc[k] = bh;

    #pragma unroll
    for (int c = 0; c < NCELL; c++) {
        const float wc = Ws[h * 37 + c];       // stride 37: conflict-free
        const float* oc = &occs[(hy * 16) * NCELL + c];
        #pragma unroll
        for (int k = 0; k < 16; k++)
            acc[k] = fmaf(oc[k * NCELL], wc, acc[k]);   // warp-broadcast
    }

    #pragma unroll
    for (int k = 0; k < 16; k++)
        out[(rbase + hy * 16 + k) * HIDDEN + h] = acc[k];   // coalesced
}

extern "C" void kernel_launch(void* const* d_in, const int* in_sizes, int n_in,
                              void* d_out, int out_size) {
    const float2* obs = (const float2*)d_in[0];   // [8192, 2] f32
    const float*  W   = (const float*) d_in[1];   // [128, 36] f32
    const float*  b   = (const float*) d_in[2];   // [128] f32
    float* out = (float*)d_out;                   // [8192, 128] f32

    dim3 g1(I_TILES, S_CHUNKS);                   // 64 x 16 = 1024 blocks
    occ_count_kernel<<<g1, T1>>>(obs);
    occ_gemm_kernel<<<N_AGENTS / ROWS2, T2>>>(W, b, out);
}

// round 12
// speedup vs baseline: 1.0455x; 1.0455x over previous
#include <cuda_runtime.h>
#include <cstdint>

// OccupancyPooling: N=8192, 6x6 relative occupancy over all 67M pairs, then
// Linear(36 -> 128).
//
// R11 = R5 EXACT (best: 45.5us; count is within ~15% of its warp-issue floor
// at ~13 inst/pair and resists further instruction cuts) + Programmatic
// Dependent Launch on the epilogue:
//  - count kernel fires cudaTriggerProgrammaticLaunchCompletion() after its
//    g_part stores
//  - gemm kernel launches with programmaticStreamSerializationAllowed=1,
//    runs its prologue (18KB W -> smem, bias load) overlapped with count's
//    tail wave, then cudaGridDependencySynchronize() before reading g_part
// Hides the inter-kernel launch gap + the gemm prologue latency (~3us).

#define N_AGENTS 8192
#define NCELL    36
#define HIDDEN   128
#define T1       128
#define CHUNK    128                    // 64 chunks * 128 = 8192 exact
#define S_CHUNKS 64
#define I_TILES  (N_AGENTS / T1)        // 64 -> grid 64x64 = 4096 blocks

#define T2       256
#define ROWS2    32                     // 256 gemm blocks

// Partial histograms [chunk][cell][agent] u8 (max count per chunk = 128).
// Fully rewritten every launch -> deterministic, no zeroing.
__device__ unsigned char g_part[S_CHUNKS][NCELL][N_AGENTS];

__device__ __forceinline__ unsigned long long pack2(float lo, float hi) {
    unsigned long long r;
    asm("mov.b64 %0, {%1, %2};" : "=l"(r) : "f"(lo), "f"(hi));
    return r;
}

// One pair, bit-exact vs reference:
//   d = rn(pj - pi)       packed FADD2 (negation exact)
//   r = rn(d*2 + 3)       packed FFMA2 (d*2 exact -> single rounding == ref)
//   m = rd(r + 2^23)      packed FADD2.RM magic floor: bits = 0x4B000000 +
//                         floor(r) for r in [0,2^23); bits < 0x4B000000 if r<0
__device__ __forceinline__ void count_pair(unsigned long long xy,
                                           unsigned long long negxy,
                                           unsigned long long two2,
                                           unsigned long long three2,
                                           unsigned long long magic2,
                                           char* __restrict__ cnt_t) {
    unsigned long long d, r, m;
    asm("add.rn.f32x2 %0, %1, %2;" : "=l"(d) : "l"(xy), "l"(negxy));
    asm("fma.rn.f32x2 %0, %1, %2, %3;" : "=l"(r) : "l"(d), "l"(two2), "l"(three2));
    asm("add.rm.f32x2 %0, %1, %2;" : "=l"(m) : "l"(r), "l"(magic2));
    unsigned bu, bv;
    asm("mov.b64 {%0, %1}, %2;" : "=r"(bu), "=r"(bv) : "l"(m));
    // byte offset: (bu*6+bv)*512 wraps (mod 2^32) to slot*512 exactly
    // (7*0x4B000000*512 == 26*2^32) -- no bias subtraction needed.
    const unsigned offb = (bu * 6u + bv) * 512u;
    if ((bu - 0x4B000000u) < 6u && (bv - 0x4B000000u) < 6u)
        *(unsigned*)(cnt_t + offb) += 1u;   // [slot][tid]: bank=tid%32, no conflicts
}

__global__ __launch_bounds__(T1, 12) void occ_count_kernel(const float2* __restrict__ obs) {
    __shared__ __align__(16) float2 sobs[CHUNK];   // 1024 B
    __shared__ unsigned cnt[NCELL * T1];           // [slot][tid], 18432 B

    const int tid = threadIdx.x;
    const int i   = blockIdx.x * T1 + tid;
    const int s   = blockIdx.y;

    sobs[tid] = obs[s * CHUNK + tid];              // one coalesced load

    #pragma unroll
    for (int c = 0; c < NCELL; c++) cnt[c * T1 + tid] = 0u;

    const float2 pi = obs[i];
    const unsigned long long negxy  = pack2(-pi.x, -pi.y);
    const unsigned long long two2   = pack2(2.0f, 2.0f);
    const unsigned long long three2 = pack2(3.0f, 3.0f);
    const unsigned long long magic2 = pack2(8388608.0f, 8388608.0f);
    char* cnt_t = (char*)(cnt + tid);

    __syncthreads();

    const float4* s4 = (const float4*)sobs;        // 2 pairs per LDS.128
    #pragma unroll 8
    for (int jj = 0; jj < CHUNK / 2; jj++) {
        const float4 p = s4[jj];
        unsigned long long xy0, xy1;
        asm("mov.b64 %0, {%1, %2};" : "=l"(xy0) : "f"(p.x), "f"(p.y));
        asm("mov.b64 %0, {%1, %2};" : "=l"(xy1) : "f"(p.z), "f"(p.w));
        count_pair(xy0, negxy, two2, three2, magic2, cnt_t);
        count_pair(xy1, negxy, two2, three2, magic2, cnt_t);
    }

    #pragma unroll
    for (int c = 0; c < NCELL; c++)
        g_part[s][c][i] = (unsigned char)cnt[c * T1 + tid];   // coalesced u8

    // Signal PDL: this block's g_part contribution is done.
    cudaTriggerProgrammaticLaunchCompletion();
}

// Fused reduce + GEMM (g_part 18.9MB is L2-hot during graph replay).
// Launched with programmatic stream serialization: prologue overlaps the
// count kernel's tail; cudaGridDependencySynchronize() gates g_part reads.
// Phase A: 288 (c, quad) items; each sums 64 u8 partials with UNSIGNED dp4a
//          byte extraction (counts can reach 128); subtract self pair
//          (bit-exact math puts j==i at rel=(3,3) -> cell 21, always).
// Phase B: out[r,:] = occs[r,:] @ W.T + b, stride-37 smem W (conflict-free).
__global__ __launch_bounds__(T2) void occ_gemm_kernel(
    const float* __restrict__ W,   // [128, 36] row-major
    const float* __restrict__ b,   // [128]
    float* __restrict__ out)       // [8192, 128]
{
    __shared__ float Ws[HIDDEN * 37];          // 18944 B
    __shared__ float occs[ROWS2 * NCELL];      // 4608 B

    const int tid   = threadIdx.x;
    const int rbase = blockIdx.x * ROWS2;

    // ---- prologue: independent of count kernel, overlapped via PDL ----
    for (int idx = tid; idx < HIDDEN * NCELL; idx += T2) {
        const int h = idx / NCELL, c = idx - h * NCELL;
        Ws[h * 37 + c] = W[idx];
    }
    const int h  = tid & (HIDDEN - 1);         // lanes -> consecutive h
    const int hy = tid >> 7;                   // row half (uniform per warp)
    const float bh = b[h];

    // ---- wait for the count grid's writes to be visible ----
    cudaGridDependencySynchronize();

    for (int id = tid; id < NCELL * (ROWS2 / 4); id += T2) {   // 288 items
        const int c = id >> 3;
        const int q = id & 7;
        unsigned a0 = 0, a1 = 0, a2 = 0, a3 = 0;
        #pragma unroll
        for (int s = 0; s < S_CHUNKS; s++) {
            const unsigned w = *(const unsigned*)&g_part[s][c][rbase + q * 4];
            a0 = __dp4a(w, 0x00000001u, a0);
            a1 = __dp4a(w, 0x00000100u, a1);
            a2 = __dp4a(w, 0x00010000u, a2);
            a3 = __dp4a(w, 0x01000000u, a3);
        }
        const float self = (c == 21) ? 1.0f : 0.0f;
        occs[(q * 4 + 0) * NCELL + c] = (float)a0 - self;
        occs[(q * 4 + 1) * NCELL + c] = (float)a1 - self;
        occs[(q * 4 + 2) * NCELL + c] = (float)a2 - self;
        occs[(q * 4 + 3) * NCELL + c] = (float)a3 - self;
    }
    __syncthreads();

    float acc[16];
    #pragma unroll
    for (int k = 0; k < 16; k++) acc[k] = bh;

    #pragma unroll
    for (int c = 0; c < NCELL; c++) {
        const float wc = Ws[h * 37 + c];       // stride 37: conflict-free
        const float* oc = &occs[(hy * 16) * NCELL + c];
        #pragma unroll
        for (int k = 0; k < 16; k++)
            acc[k] = fmaf(oc[k * NCELL], wc, acc[k]);   // warp-broadcast
    }

    #pragma unroll
    for (int k = 0; k < 16; k++)
        out[(rbase + hy * 16 + k) * HIDDEN + h] = acc[k];   // coalesced
}

extern "C" void kernel_launch(void* const* d_in, const int* in_sizes, int n_in,
                              void* d_out, int out_size) {
    const float2* obs = (const float2*)d_in[0];   // [8192, 2] f32
    const float*  W   = (const float*) d_in[1];   // [128, 36] f32
    const float*  bb  = (const float*) d_in[2];   // [128] f32
    float* out = (float*)d_out;                   // [8192, 128] f32

    dim3 g1(I_TILES, S_CHUNKS);                   // 64 x 64 = 4096 blocks
    occ_count_kernel<<<g1, T1>>>(obs);

    // Epilogue with Programmatic Dependent Launch: prologue overlaps the
    // count kernel's tail; correctness gated by cudaGridDependencySynchronize.
    cudaLaunchConfig_t cfg = {};
    cfg.gridDim  = dim3(N_AGENTS / ROWS2, 1, 1);  // 256 blocks
    cfg.blockDim = dim3(T2, 1, 1);
    cfg.dynamicSmemBytes = 0;
    cfg.stream = (cudaStream_t)0;                 // same (capture) stream
    cudaLaunchAttribute attr[1];
    attr[0].id = cudaLaunchAttributeProgrammaticStreamSerialization;
    attr[0].val.programmaticStreamSerializationAllowed = 1;
    cfg.attrs = attr;
    cfg.numAttrs = 1;
    cudaLaunchKernelEx(&cfg, occ_gemm_kernel, W, bb, out);
}

// round 13
// speedup vs baseline: 1.0829x; 1.0358x over previous
#include <cuda_runtime.h>
#include <cstdint>

// OccupancyPooling: N=8192, 6x6 relative occupancy over all 67M pairs, then
// Linear(36 -> 128).
//
// R12 = R5 (best: 45.5us) with ONE change, PDL reverted (R11 lost 1.7us to
// secondary-grid SM squatting):
//  - j-data loaded as ulonglong2 instead of float4+asm-pack: float2 memory
//    layout IS the packed (x,y) u64, so LDS.128 delivers both pairs already
//    in aligned register pairs and the two mov.b64 packs per pair vanish
//    (~2 of ~13 inst/pair if ptxas was materializing them).
//  - everything else byte-identical to R5: bit-exact 3-op packed math,
//    [slot][tid] conflict-free counters, 64x64 grid / 12 blocks/SM,
//    fused dp4a reduce + ROWS2=32 broadcast GEMM epilogue.

#define N_AGENTS 8192
#define NCELL    36
#define HIDDEN   128
#define T1       128
#define CHUNK    128                    // 64 chunks * 128 = 8192 exact
#define S_CHUNKS 64
#define I_TILES  (N_AGENTS / T1)        // 64 -> grid 64x64 = 4096 blocks

#define T2       256
#define ROWS2    32                     // 256 gemm blocks

// Partial histograms [chunk][cell][agent] u8 (max count per chunk = 128).
// Fully rewritten every launch -> deterministic, no zeroing.
__device__ unsigned char g_part[S_CHUNKS][NCELL][N_AGENTS];

__device__ __forceinline__ unsigned long long pack2(float lo, float hi) {
    unsigned long long r;
    asm("mov.b64 %0, {%1, %2};" : "=l"(r) : "f"(lo), "f"(hi));
    return r;
}

// One pair, bit-exact vs reference:
//   d = rn(pj - pi)       packed FADD2 (negation exact)
//   r = rn(d*2 + 3)       packed FFMA2 (d*2 exact -> single rounding == ref)
//   m = rd(r + 2^23)      packed FADD2.RM magic floor: bits = 0x4B000000 +
//                         floor(r) for r in [0,2^23); bits < 0x4B000000 if r<0
__device__ __forceinline__ void count_pair(unsigned long long xy,
                                           unsigned long long negxy,
                                           unsigned long long two2,
                                           unsigned long long three2,
                                           unsigned long long magic2,
                                           char* __restrict__ cnt_t) {
    unsigned long long d, r, m;
    asm("add.rn.f32x2 %0, %1, %2;" : "=l"(d) : "l"(xy), "l"(negxy));
    asm("fma.rn.f32x2 %0, %1, %2, %3;" : "=l"(r) : "l"(d), "l"(two2), "l"(three2));
    asm("add.rm.f32x2 %0, %1, %2;" : "=l"(m) : "l"(r), "l"(magic2));
    unsigned bu, bv;
    asm("mov.b64 {%0, %1}, %2;" : "=r"(bu), "=r"(bv) : "l"(m));   // pair-alias, no MOV
    // byte offset: (bu*6+bv)*512 wraps (mod 2^32) to slot*512 exactly
    // (7*0x4B000000*512 == 26*2^32) -- no bias subtraction needed.
    const unsigned offb = (bu * 6u + bv) * 512u;
    if ((bu - 0x4B000000u) < 6u && (bv - 0x4B000000u) < 6u)
        *(unsigned*)(cnt_t + offb) += 1u;   // [slot][tid]: bank=tid%32, no conflicts
}

__global__ __launch_bounds__(T1, 12) void occ_count_kernel(const float2* __restrict__ obs) {
    __shared__ __align__(16) float2 sobs[CHUNK];   // 1024 B
    __shared__ unsigned cnt[NCELL * T1];           // [slot][tid], 18432 B

    const int tid = threadIdx.x;
    const int i   = blockIdx.x * T1 + tid;
    const int s   = blockIdx.y;

    sobs[tid] = obs[s * CHUNK + tid];              // one coalesced load

    #pragma unroll
    for (int c = 0; c < NCELL; c++) cnt[c * T1 + tid] = 0u;

    const float2 pi = obs[i];
    const unsigned long long negxy  = pack2(-pi.x, -pi.y);
    const unsigned long long two2   = pack2(2.0f, 2.0f);
    const unsigned long long three2 = pack2(3.0f, 3.0f);
    const unsigned long long magic2 = pack2(8388608.0f, 8388608.0f);
    char* cnt_t = (char*)(cnt + tid);

    __syncthreads();

    // float2 memory layout == packed u64 (x,y): LDS.128 as ulonglong2 gives
    // both pairs directly in aligned register pairs -- zero pack MOVs.
    const ulonglong2* s8 = (const ulonglong2*)sobs;   // 2 pairs per LDS.128
    #pragma unroll 8
    for (int jj = 0; jj < CHUNK / 2; jj++) {
        const ulonglong2 q = s8[jj];
        count_pair(q.x, negxy, two2, three2, magic2, cnt_t);
        count_pair(q.y, negxy, two2, three2, magic2, cnt_t);
    }

    #pragma unroll
    for (int c = 0; c < NCELL; c++)
        g_part[s][c][i] = (unsigned char)cnt[c * T1 + tid];   // coalesced u8

}

// Fused reduce + GEMM (g_part 18.9MB is L2-hot during graph replay).
// Phase A: 288 (c, quad) items; each sums 64 u8 partials with UNSIGNED dp4a
//          byte extraction (counts can reach 128); subtract self pair
//          (bit-exact math puts j==i at rel=(3,3) -> cell 21, always).
// Phase B: out[r,:] = occs[r,:] @ W.T + b, stride-37 smem W (conflict-free).
__global__ __launch_bounds__(T2) void occ_gemm_kernel(
    const float* __restrict__ W,   // [128, 36] row-major
    const float* __restrict__ b,   // [128]
    float* __restrict__ out)       // [8192, 128]
{
    __shared__ float Ws[HIDDEN * 37];          // 18944 B
    __shared__ float occs[ROWS2 * NCELL];      // 4608 B

    const int tid   = threadIdx.x;
    const int rbase = blockIdx.x * ROWS2;

    for (int idx = tid; idx < HIDDEN * NCELL; idx += T2) {
        const int h = idx / NCELL, c = idx - h * NCELL;
        Ws[h * 37 + c] = W[idx];
    }

    for (int id = tid; id < NCELL * (ROWS2 / 4); id += T2) {   // 288 items
        const int c = id >> 3;
        const int q = id & 7;
        unsigned a0 = 0, a1 = 0, a2 = 0, a3 = 0;
        #pragma unroll
        for (int s = 0; s < S_CHUNKS; s++) {
            const unsigned w = *(const unsigned*)&g_part[s][c][rbase + q * 4];
            a0 = __dp4a(w, 0x00000001u, a0);
            a1 = __dp4a(w, 0x00000100u, a1);
            a2 = __dp4a(w, 0x00010000u, a2);
            a3 = __dp4a(w, 0x01000000u, a3);
        }
        const float self = (c == 21) ? 1.0f : 0.0f;
        occs[(q * 4 + 0) * NCELL + c] = (float)a0 - self;
        occs[(q * 4 + 1) * NCELL + c] = (float)a1 - self;
        occs[(q * 4 + 2) * NCELL + c] = (float)a2 - self;
        occs[(q * 4 + 3) * NCELL + c] = (float)a3 - self;
    }
    __syncthreads();

    const int h  = tid & (HIDDEN - 1);         // lanes -> consecutive h
    const int hy = tid >> 7;                   // row half (uniform per warp)
    const float bh = b[h];

    float acc[16];
    #pragma unroll
    for (int k = 0; k < 16; k++) acc[k] = bh;

    #pragma unroll
    for (int c = 0; c < NCELL; c++) {
        const float wc = Ws[h * 37 + c];       // stride 37: conflict-free
        const float* oc = &occs[(hy * 16) * NCELL + c];
        #pragma unroll
        for (int k = 0; k < 16; k++)
            acc[k] = fmaf(oc[k * NCELL], wc, acc[k]);   // warp-broadcast
    }

    #pragma unroll
    for (int k = 0; k < 16; k++)
        out[(rbase + hy * 16 + k) * HIDDEN + h] = acc[k];   // coalesced
}

extern "C" void kernel_launch(void* const* d_in, const int* in_sizes, int n_in,
                              void* d_out, int out_size) {
    const float2* obs = (const float2*)d_in[0];   // [8192, 2] f32
    const float*  W   = (const float*) d_in[1];   // [128, 36] f32
    const float*  b   = (const float*) d_in[2];   // [128] f32
    float* out = (float*)d_out;                   // [8192, 128] f32

    dim3 g1(I_TILES, S_CHUNKS);                   // 64 x 64 = 4096 blocks
    occ_count_kernel<<<g1, T1>>>(obs);
    occ_gemm_kernel<<<N_AGENTS / ROWS2, T2>>>(W, b, out);
}